// round 13
// baseline (speedup 1.0000x reference)
#include <cuda_runtime.h>
#include <cuda_bf16.h>
#include <cstdint>

#define Bq 32
#define Cc 64
#define Nn 1024

// ---------------- scratch (device globals) ----------------------------------
__device__ __nv_bfloat16 g_phiH[Bq * Cc * Nn];  // [b][c][m]
__device__ __nv_bfloat16 g_phiL[Bq * Cc * Nn];
__device__ __nv_bfloat16 g_wmkH[Nn * Nn];       // [k][m]
__device__ __nv_bfloat16 g_wmkL[Nn * Nn];
__device__ __nv_bfloat16 g_thH[Bq * Cc * Nn];   // [b][c][n] theta hi/lo
__device__ __nv_bfloat16 g_thL[Bq * Cc * Nn];
__device__ __nv_bfloat16 g_PH[Bq * Cc * Nn];    // [b][c][k] P hi/lo
__device__ __nv_bfloat16 g_PL[Bq * Cc * Nn];
__device__ float g_gm[Bq * Cc * Nn];            // [b][c][n]
__device__ __nv_bfloat16 g_EH[(size_t)Bq * Nn * Nn];  // [b][k][n] exp hi (64MB)
__device__ __nv_bfloat16 g_EL[(size_t)Bq * Nn * Nn];  // [b][k][n] exp lo (64MB)
__device__ float g_Z[Bq * Nn];
__device__ __nv_bfloat16 g_gzH[Bq * Cc * Nn];   // [b][o][m] (w_mask@gm)/Z hi/lo
__device__ __nv_bfloat16 g_gzL[Bq * Cc * Nn];
// small weight splits (filled by k0)
__device__ __nv_bfloat16 g_wphiH[Cc * Cc], g_wphiL[Cc * Cc];
__device__ __nv_bfloat16 g_wthH[Cc * Cc],  g_wthL[Cc * Cc];
__device__ __nv_bfloat16 g_wgvH[Cc * Cc],  g_wgvL[Cc * Cc];
__device__ __nv_bfloat16 g_wmaskH[Cc * Cc], g_wmaskL[Cc * Cc];

// ---------------- mma.sync / cp.async helpers -------------------------------
__device__ __forceinline__ uint32_t smem_u32(const void* p) {
    uint32_t a;
    asm("{ .reg .u64 t; cvta.to.shared.u64 t, %1; cvt.u32.u64 %0, t; }"
        : "=r"(a) : "l"(p));
    return a;
}
__device__ __forceinline__ void ldsm_x4(uint32_t addr, uint32_t r[4]) {
    asm volatile("ldmatrix.sync.aligned.m8n8.x4.shared.b16 {%0,%1,%2,%3}, [%4];"
                 : "=r"(r[0]), "=r"(r[1]), "=r"(r[2]), "=r"(r[3]) : "r"(addr));
}
__device__ __forceinline__ void ldsm_x4t(uint32_t addr, uint32_t r[4]) {
    asm volatile("ldmatrix.sync.aligned.m8n8.x4.trans.shared.b16 {%0,%1,%2,%3}, [%4];"
                 : "=r"(r[0]), "=r"(r[1]), "=r"(r[2]), "=r"(r[3]) : "r"(addr));
}
__device__ __forceinline__ void mma_bf16(float4& d, const uint32_t a[4],
                                         uint32_t b0, uint32_t b1) {
    asm volatile(
        "mma.sync.aligned.m16n8k16.row.col.f32.bf16.bf16.f32 "
        "{%0,%1,%2,%3}, {%4,%5,%6,%7}, {%8,%9}, {%0,%1,%2,%3};"
        : "+f"(d.x), "+f"(d.y), "+f"(d.z), "+f"(d.w)
        : "r"(a[0]), "r"(a[1]), "r"(a[2]), "r"(a[3]), "r"(b0), "r"(b1));
}
__device__ __forceinline__ void cpa16(uint32_t s, const void* g) {
    asm volatile("cp.async.cg.shared.global [%0], [%1], 16;" :: "r"(s), "l"(g));
}
#define CPA_COMMIT() asm volatile("cp.async.commit_group;" ::: "memory")
#define CPA_WAIT(n) asm volatile("cp.async.wait_group %0;" :: "n"(n) : "memory")

__device__ __forceinline__ uint32_t bfpack(float a, float b) {
    __nv_bfloat162 h;
    h.x = __float2bfloat16(a); h.y = __float2bfloat16(b);
    return *(uint32_t*)&h;
}
__device__ __forceinline__ void split4(float4 v, uint2& hi, uint2& lo) {
    uint32_t hA = bfpack(v.x, v.y), hB = bfpack(v.z, v.w);
    __nv_bfloat162* hp = (__nv_bfloat162*)&hA;
    __nv_bfloat162* hq = (__nv_bfloat162*)&hB;
    uint32_t lA = bfpack(v.x - __bfloat162float(hp->x), v.y - __bfloat162float(hp->y));
    uint32_t lB = bfpack(v.z - __bfloat162float(hq->x), v.w - __bfloat162float(hq->y));
    hi = make_uint2(hA, hB); lo = make_uint2(lA, lB);
}
__device__ __forceinline__ void split2(float a, float b, uint32_t& h, uint32_t& l) {
    h = bfpack(a, b);
    __nv_bfloat162* hp = (__nv_bfloat162*)&h;
    l = bfpack(a - __bfloat162float(hp->x), b - __bfloat162float(hp->y));
}

// ---------------- K0: wmk split + zero Z + small weights (merged) -----------
__global__ __launch_bounds__(256) void k0_all(
    const float* __restrict__ wmk, const float* __restrict__ wmv,
    const float* __restrict__ wg, const float* __restrict__ wphi,
    const float* __restrict__ wtheta, const float* __restrict__ wmask) {
    int t = blockIdx.x * 256 + threadIdx.x;   // 0..262143
    float4 v = ((const float4*)wmk)[t];
    uint2 hi, lo;
    split4(v, hi, lo);
    ((uint2*)g_wmkH)[t] = hi;
    ((uint2*)g_wmkL)[t] = lo;
    if (t < Bq * Nn) g_Z[t] = 0.0f;
    if (t < Cc * Cc) {
        int d = t >> 6, ci = t & 63;
        float s = 0.0f;
#pragma unroll
        for (int c = 0; c < 64; c++) s += wmv[d * 64 + c] * wg[c * 64 + ci];
        __nv_bfloat16 h;
        h = __float2bfloat16(s);
        g_wgvH[t] = h; g_wgvL[t] = __float2bfloat16(s - __bfloat162float(h));
        float u = wphi[t];
        h = __float2bfloat16(u);
        g_wphiH[t] = h; g_wphiL[t] = __float2bfloat16(u - __bfloat162float(h));
        u = wtheta[t];
        h = __float2bfloat16(u);
        g_wthH[t] = h; g_wthL[t] = __float2bfloat16(u - __bfloat162float(h));
        u = wmask[t];
        h = __float2bfloat16(u);
        g_wmaskH[t] = h; g_wmaskL[t] = __float2bfloat16(u - __bfloat162float(h));
    }
}

// ---------------- K1: channel GEMMs via mma.sync (phi, theta, gm) -----------
__global__ __launch_bounds__(256, 2) void k1_mma(const float* __restrict__ x) {
    extern __shared__ __align__(16) char sm1[];
    __nv_bfloat16* sXh = (__nv_bfloat16*)sm1;
    __nv_bfloat16* sXl = (__nv_bfloat16*)(sm1 + 17408);
    __nv_bfloat16* sW[6] = {
        (__nv_bfloat16*)(sm1 + 34816), (__nv_bfloat16*)(sm1 + 44032),
        (__nv_bfloat16*)(sm1 + 53248), (__nv_bfloat16*)(sm1 + 62464),
        (__nv_bfloat16*)(sm1 + 71680), (__nv_bfloat16*)(sm1 + 80896)};
    int b = blockIdx.x, n0 = blockIdx.y << 7;
    int t = threadIdx.x, w = t >> 5, lane = t & 31;
    int cgrp = w & 3, ngrp = w >> 2;

#pragma unroll
    for (int i = 0; i < 8; i++) {
        int lin = t + (i << 8);
        int r = lin >> 5, q = lin & 31;
        float4 v = *(const float4*)&x[((size_t)(b << 6) + r) * Nn + n0 + (q << 2)];
        uint2 hi, lo;
        split4(v, hi, lo);
        *(uint2*)&sXh[r * 136 + (q << 2)] = hi;
        *(uint2*)&sXl[r * 136 + (q << 2)] = lo;
    }
    {
        const __nv_bfloat16* src[6] = {g_wphiH, g_wphiL, g_wthH, g_wthL, g_wgvH, g_wgvL};
#pragma unroll
        for (int a = 0; a < 6; a++)
#pragma unroll
            for (int i = 0; i < 2; i++) {
                int lin = t + (i << 8);
                int r = lin >> 3, q = lin & 7;
                *(uint4*)&sW[a][r * 72 + (q << 3)] = *(const uint4*)&src[a][r * 64 + (q << 3)];
            }
    }
    __syncthreads();

    int lr = lane & 15, lh = lane >> 4;
    int bq = lane >> 3, br = lane & 7;

#pragma unroll
    for (int p = 0; p < 3; p++) {
        float4 acc[8] = {};
        __nv_bfloat16* WH = sW[p * 2];
        __nv_bfloat16* WL = sW[p * 2 + 1];
#pragma unroll
        for (int kk = 0; kk < 4; kk++) {
            uint32_t ah[4], al[4];
            ldsm_x4(smem_u32(&WH[(cgrp * 16 + lr) * 72 + kk * 16 + lh * 8]), ah);
            ldsm_x4(smem_u32(&WL[(cgrp * 16 + lr) * 72 + kk * 16 + lh * 8]), al);
#pragma unroll
            for (int j = 0; j < 4; j++) {
                int rowk = (kk << 4) + ((bq & 1) << 3) + br;
                int coln = (ngrp << 6) + (j << 4) + ((bq >> 1) << 3);
                uint32_t bh[4], bl[4];
                ldsm_x4t(smem_u32(&sXh[rowk * 136 + coln]), bh);
                mma_bf16(acc[j * 2], ah, bh[0], bh[1]);
                mma_bf16(acc[j * 2 + 1], ah, bh[2], bh[3]);
                mma_bf16(acc[j * 2], al, bh[0], bh[1]);
                mma_bf16(acc[j * 2 + 1], al, bh[2], bh[3]);
                ldsm_x4t(smem_u32(&sXl[rowk * 136 + coln]), bl);
                mma_bf16(acc[j * 2], ah, bl[0], bl[1]);
                mma_bf16(acc[j * 2 + 1], ah, bl[2], bl[3]);
            }
        }
        int m = (cgrp << 4) + (lane >> 2);
        if (p == 2) {
            float* O = g_gm + (size_t)(b << 6) * Nn;
#pragma unroll
            for (int f = 0; f < 8; f++) {
                int n = n0 + (ngrp << 6) + ((f >> 1) << 4) + ((f & 1) << 3) + ((lane & 3) << 1);
                *(float2*)&O[(size_t)m * Nn + n] = make_float2(acc[f].x, acc[f].y);
                *(float2*)&O[(size_t)(m + 8) * Nn + n] = make_float2(acc[f].z, acc[f].w);
            }
        } else {
            __nv_bfloat16* H = (p == 0 ? g_phiH : g_thH);
            __nv_bfloat16* L = (p == 0 ? g_phiL : g_thL);
            size_t rowa = ((size_t)(b << 6) + m) * Nn;
            size_t rowb2 = ((size_t)(b << 6) + m + 8) * Nn;
#pragma unroll
            for (int f = 0; f < 8; f++) {
                int n = n0 + (ngrp << 6) + ((f >> 1) << 4) + ((f & 1) << 3) + ((lane & 3) << 1);
                uint32_t h, l;
                split2(acc[f].x, acc[f].y, h, l);
                *(uint32_t*)&H[rowa + n] = h;
                *(uint32_t*)&L[rowa + n] = l;
                split2(acc[f].z, acc[f].w, h, l);
                *(uint32_t*)&H[rowb2 + n] = h;
                *(uint32_t*)&L[rowb2 + n] = l;
            }
        }
    }
}

// ---------------- K2: P = phi @ wmk^T (4 warps, 16c x 128k, cp.async) -------
__global__ __launch_bounds__(128, 2) void k2_P_mma(void) {
    extern __shared__ __align__(16) char sm2[];
    uint32_t sb = smem_u32(sm2);
    int b = blockIdx.x, k0 = blockIdx.y << 7;
    int t = threadIdx.x, w = t >> 5, lane = t & 31;

    const __nv_bfloat16* Ah = g_phiH + (size_t)(b << 6) * Nn;
    const __nv_bfloat16* Al = g_phiL + (size_t)(b << 6) * Nn;

    float4 acc[16] = {};
    int lr = lane & 15, lh = lane >> 4;
    int bq = lane >> 3, br = lane & 7;

    auto stage = [&](int mc, int buf) {
        uint32_t base = sb + buf * 55296u;
        uint32_t aH = base, aL = base + 9216u, bH = base + 18432u, bL = base + 36864u;
#pragma unroll
        for (int i = 0; i < 4; i++) {
            int lin = t + (i << 7);
            int r = lin >> 3, q = lin & 7;
            cpa16(aH + r * 144 + (q << 4), &Ah[(size_t)r * Nn + mc + (q << 3)]);
            cpa16(aL + r * 144 + (q << 4), &Al[(size_t)r * Nn + mc + (q << 3)]);
        }
#pragma unroll
        for (int i = 0; i < 8; i++) {
            int lin = t + (i << 7);
            int r = lin >> 3, q = lin & 7;
            cpa16(bH + r * 144 + (q << 4), &g_wmkH[(size_t)(k0 + r) * Nn + mc + (q << 3)]);
            cpa16(bL + r * 144 + (q << 4), &g_wmkL[(size_t)(k0 + r) * Nn + mc + (q << 3)]);
        }
        CPA_COMMIT();
    };

    stage(0, 0);
    for (int ci = 0; ci < 16; ci++) {
        int buf = ci & 1;
        if (ci + 1 < 16) { stage((ci + 1) << 6, buf ^ 1); CPA_WAIT(1); }
        else { CPA_WAIT(0); }
        __syncthreads();
        uint32_t base = sb + buf * 55296u;
        uint32_t aH = base, aL = base + 9216u, bH = base + 18432u, bL = base + 36864u;
#pragma unroll
        for (int kk = 0; kk < 4; kk++) {
            uint32_t ah[4], al[4];
            uint32_t arow = (w * 16 + lr) * 144 + kk * 32 + lh * 16;
            ldsm_x4(aH + arow, ah);
            ldsm_x4(aL + arow, al);
#pragma unroll
            for (int j = 0; j < 8; j++) {
                int rowb = (j << 4) + ((bq >> 1) << 3) + br;
                uint32_t boff = rowb * 144 + kk * 32 + ((bq & 1) << 4);
                uint32_t bh[4], bl[4];
                ldsm_x4(bH + boff, bh);
                mma_bf16(acc[j * 2], ah, bh[0], bh[1]);
                mma_bf16(acc[j * 2 + 1], ah, bh[2], bh[3]);
                mma_bf16(acc[j * 2], al, bh[0], bh[1]);
                mma_bf16(acc[j * 2 + 1], al, bh[2], bh[3]);
                ldsm_x4(bL + boff, bl);
                mma_bf16(acc[j * 2], ah, bl[0], bl[1]);
                mma_bf16(acc[j * 2 + 1], ah, bl[2], bl[3]);
            }
        }
        __syncthreads();
    }

    int m = (w << 4) + (lane >> 2);
    size_t prow = ((size_t)(b << 6) + m) * Nn + k0;
#pragma unroll
    for (int f = 0; f < 16; f++) {
        int n = ((f >> 1) << 4) + ((f & 1) << 3) + ((lane & 3) << 1);
        uint32_t h, l;
        split2(acc[f].x, acc[f].y, h, l);
        *(uint32_t*)&g_PH[prow + n] = h;
        *(uint32_t*)&g_PL[prow + n] = l;
        split2(acc[f].z, acc[f].w, h, l);
        *(uint32_t*)&g_PH[prow + 8 * Nn + n] = h;
        *(uint32_t*)&g_PL[prow + 8 * Nn + n] = l;
    }
}

// ---------------- K3: Et = exp(P^T theta), smem epilogue --------------------
// grid (8 ntile, 8 ktile, 32 b): consecutive CTAs share P tile, write full E rows
__global__ __launch_bounds__(256, 2) void k3_att_mma(void) {
    extern __shared__ __align__(16) char sm3[];
    __nv_bfloat16* sPh = (__nv_bfloat16*)sm3;              // [64][136]
    __nv_bfloat16* sPl = (__nv_bfloat16*)(sm3 + 17408);
    __nv_bfloat16* sTh = (__nv_bfloat16*)(sm3 + 34816);
    __nv_bfloat16* sTl = (__nv_bfloat16*)(sm3 + 52224);
    int b = blockIdx.z, k0 = blockIdx.y << 7, n0 = blockIdx.x << 7;
    int t = threadIdx.x, w = t >> 5, lane = t & 31;
    int kw = w & 3, nw = w >> 2;

#pragma unroll
    for (int i = 0; i < 4; i++) {
        int lin = t + (i << 8);
        int r = lin >> 4, q = lin & 15;
        size_t pofs = ((size_t)(b << 6) + r) * Nn + k0 + (q << 3);
        size_t tofs = ((size_t)(b << 6) + r) * Nn + n0 + (q << 3);
        *(uint4*)&sPh[r * 136 + (q << 3)] = *(const uint4*)&g_PH[pofs];
        *(uint4*)&sPl[r * 136 + (q << 3)] = *(const uint4*)&g_PL[pofs];
        *(uint4*)&sTh[r * 136 + (q << 3)] = *(const uint4*)&g_thH[tofs];
        *(uint4*)&sTl[r * 136 + (q << 3)] = *(const uint4*)&g_thL[tofs];
    }
    __syncthreads();

    float4 acc[2][8] = {};
    int bq = lane >> 3, br = lane & 7;
#pragma unroll
    for (int kk = 0; kk < 4; kk++) {
        int c0 = kk << 4;
        uint32_t ah[2][4], al[2][4];
#pragma unroll
        for (int mt = 0; mt < 2; mt++) {
            int m0 = (kw << 5) + (mt << 4);
            int rowc = c0 + ((bq >> 1) << 3) + br;
            int colm = m0 + ((bq & 1) << 3);
            ldsm_x4t(smem_u32(&sPh[rowc * 136 + colm]), ah[mt]);
            ldsm_x4t(smem_u32(&sPl[rowc * 136 + colm]), al[mt]);
        }
#pragma unroll
        for (int j = 0; j < 4; j++) {
            int rowc = c0 + ((bq & 1) << 3) + br;
            int coln = (nw << 6) + (j << 4) + ((bq >> 1) << 3);
            uint32_t bh[4], bl[4];
            ldsm_x4t(smem_u32(&sTh[rowc * 136 + coln]), bh);
            ldsm_x4t(smem_u32(&sTl[rowc * 136 + coln]), bl);
#pragma unroll
            for (int mt = 0; mt < 2; mt++) {
                mma_bf16(acc[mt][j * 2], ah[mt], bh[0], bh[1]);
                mma_bf16(acc[mt][j * 2 + 1], ah[mt], bh[2], bh[3]);
                mma_bf16(acc[mt][j * 2], al[mt], bh[0], bh[1]);
                mma_bf16(acc[mt][j * 2 + 1], al[mt], bh[2], bh[3]);
                mma_bf16(acc[mt][j * 2], ah[mt], bl[0], bl[1]);
                mma_bf16(acc[mt][j * 2 + 1], ah[mt], bl[2], bl[3]);
            }
        }
    }

    __syncthreads();
    __nv_bfloat16* sEH = (__nv_bfloat16*)sm3;
    __nv_bfloat16* sEL = (__nv_bfloat16*)(sm3 + 34816);
#pragma unroll
    for (int mt = 0; mt < 2; mt++) {
        int krow = (kw << 5) + (mt << 4) + (lane >> 2);
        float sA = 0.f, sB = 0.f;
#pragma unroll
        for (int j = 0; j < 8; j++) {
            int nc = (nw << 6) + (j << 3) + ((lane & 3) << 1);
            float ex = __expf(acc[mt][j].x), ey = __expf(acc[mt][j].y);
            float ez = __expf(acc[mt][j].z), ew = __expf(acc[mt][j].w);
            sA += ex + ey; sB += ez + ew;
            uint32_t h0, l0, h1, l1;
            split2(ex, ey, h0, l0);
            split2(ez, ew, h1, l1);
            *(uint32_t*)&sEH[krow * 136 + nc] = h0;
            *(uint32_t*)&sEL[krow * 136 + nc] = l0;
            *(uint32_t*)&sEH[(krow + 8) * 136 + nc] = h1;
            *(uint32_t*)&sEL[(krow + 8) * 136 + nc] = l1;
        }
        sA += __shfl_xor_sync(0xffffffffu, sA, 1);
        sA += __shfl_xor_sync(0xffffffffu, sA, 2);
        sB += __shfl_xor_sync(0xffffffffu, sB, 1);
        sB += __shfl_xor_sync(0xffffffffu, sB, 2);
        if ((lane & 3) == 0) {
            atomicAdd(&g_Z[b * Nn + k0 + krow], sA);
            atomicAdd(&g_Z[b * Nn + k0 + krow + 8], sB);
        }
    }
    __syncthreads();
#pragma unroll
    for (int i = 0; i < 8; i++) {
        int lin = t + (i << 8);
        int r = lin >> 4, q = lin & 15;
        size_t off = ((size_t)(b * Nn + k0 + r)) * Nn + n0 + (q << 3);
        *(uint4*)&g_EH[off] = *(uint4*)&sEH[r * 136 + (q << 3)];
        *(uint4*)&g_EL[off] = *(uint4*)&sEL[r * 136 + (q << 3)];
    }
}

// ---------------- K5: gz = (wmask@gm)/Z via mma.sync, bf16 hi/lo out --------
__global__ __launch_bounds__(256, 2) void k5_gmz_mma(void) {
    extern __shared__ __align__(16) char sm5[];
    __nv_bfloat16* sGh = (__nv_bfloat16*)sm5;
    __nv_bfloat16* sGl = (__nv_bfloat16*)(sm5 + 17408);
    __nv_bfloat16* sWh = (__nv_bfloat16*)(sm5 + 34816);
    __nv_bfloat16* sWl = (__nv_bfloat16*)(sm5 + 44032);
    float* szm = (float*)(sm5 + 53248);
    int b = blockIdx.x, m0 = blockIdx.y << 7;
    int t = threadIdx.x, w = t >> 5, lane = t & 31;
    int ogrp = w & 3, mgrp = w >> 2;

    const float* gm = g_gm + (size_t)(b << 6) * Nn;
#pragma unroll
    for (int i = 0; i < 8; i++) {
        int lin = t + (i << 8);
        int r = lin >> 5, q = lin & 31;
        float4 v = *(const float4*)&gm[(size_t)r * Nn + m0 + (q << 2)];
        uint2 hi, lo;
        split4(v, hi, lo);
        *(uint2*)&sGh[r * 136 + (q << 2)] = hi;
        *(uint2*)&sGl[r * 136 + (q << 2)] = lo;
    }
#pragma unroll
    for (int i = 0; i < 2; i++) {
        int lin = t + (i << 8);
        int r = lin >> 3, q = lin & 7;
        *(uint4*)&sWh[r * 72 + (q << 3)] = *(const uint4*)&g_wmaskH[r * 64 + (q << 3)];
        *(uint4*)&sWl[r * 72 + (q << 3)] = *(const uint4*)&g_wmaskL[r * 64 + (q << 3)];
    }
    if (t < 128) szm[t] = 1.0f / g_Z[b * Nn + m0 + t];
    __syncthreads();

    int lr = lane & 15, lh = lane >> 4;
    int bq = lane >> 3, br = lane & 7;

    float4 acc[8] = {};
#pragma unroll
    for (int kk = 0; kk < 4; kk++) {
        uint32_t ah[4], al[4];
        ldsm_x4(smem_u32(&sWh[(ogrp * 16 + lr) * 72 + kk * 16 + lh * 8]), ah);
        ldsm_x4(smem_u32(&sWl[(ogrp * 16 + lr) * 72 + kk * 16 + lh * 8]), al);
#pragma unroll
        for (int j = 0; j < 4; j++) {
            int rowk = (kk << 4) + ((bq & 1) << 3) + br;
            int colm = (mgrp << 6) + (j << 4) + ((bq >> 1) << 3);
            uint32_t bh[4], bl[4];
            ldsm_x4t(smem_u32(&sGh[rowk * 136 + colm]), bh);
            mma_bf16(acc[j * 2], ah, bh[0], bh[1]);
            mma_bf16(acc[j * 2 + 1], ah, bh[2], bh[3]);
            mma_bf16(acc[j * 2], al, bh[0], bh[1]);
            mma_bf16(acc[j * 2 + 1], al, bh[2], bh[3]);
            ldsm_x4t(smem_u32(&sGl[rowk * 136 + colm]), bl);
            mma_bf16(acc[j * 2], ah, bl[0], bl[1]);
            mma_bf16(acc[j * 2 + 1], ah, bl[2], bl[3]);
        }
    }
    int o = (ogrp << 4) + (lane >> 2);
    size_t rowa = ((size_t)(b << 6) + o) * Nn + m0;
    size_t rowb2 = ((size_t)(b << 6) + o + 8) * Nn + m0;
#pragma unroll
    for (int f = 0; f < 8; f++) {
        int mm = (mgrp << 6) + ((f >> 1) << 4) + ((f & 1) << 3) + ((lane & 3) << 1);
        float i0 = szm[mm], i1 = szm[mm + 1];
        uint32_t h, l;
        split2(acc[f].x * i0, acc[f].y * i1, h, l);
        *(uint32_t*)&g_gzH[rowa + mm] = h;
        *(uint32_t*)&g_gzL[rowa + mm] = l;
        split2(acc[f].z * i0, acc[f].w * i1, h, l);
        *(uint32_t*)&g_gzH[rowb2 + mm] = h;
        *(uint32_t*)&g_gzL[rowb2 + mm] = l;
    }
}

// ---------------- K4: out = gz @ E + x (4 warps, 16o x 128n, cp.async) ------
// grid (8 ntile, 32 b): consecutive CTAs share b -> gz + E row L2 dedup
__global__ __launch_bounds__(128, 2) void k4_out_mma(
    const float* __restrict__ x, float* __restrict__ out) {
    extern __shared__ __align__(16) char sm4[];
    uint32_t sb = smem_u32(sm4);
    int b = blockIdx.y, n0 = blockIdx.x << 7;
    int t = threadIdx.x, w = t >> 5, lane = t & 31;

    float4 acc[16] = {};
    int lr = lane & 15, lh = lane >> 4;
    int bq = lane >> 3, br = lane & 7;

    auto stage = [&](int mc, int buf) {
        uint32_t base = sb + buf * 53248u;
        uint32_t aH = base, aL = base + 9216u, bH = base + 18432u, bL = base + 35840u;
#pragma unroll
        for (int i = 0; i < 4; i++) {
            int lin = t + (i << 7);
            int r = lin >> 3, q = lin & 7;
            size_t gofs = ((size_t)(b << 6) + r) * Nn + mc + (q << 3);
            cpa16(aH + r * 144 + (q << 4), &g_gzH[gofs]);
            cpa16(aL + r * 144 + (q << 4), &g_gzL[gofs]);
        }
#pragma unroll
        for (int i = 0; i < 8; i++) {
            int lin = t + (i << 7);
            int r = lin >> 4, q = lin & 15;
            size_t off = ((size_t)(b * Nn) + mc + r) * Nn + n0 + (q << 3);
            cpa16(bH + r * 272 + (q << 4), &g_EH[off]);
            cpa16(bL + r * 272 + (q << 4), &g_EL[off]);
        }
        CPA_COMMIT();
    };

    stage(0, 0);
    for (int ci = 0; ci < 16; ci++) {
        int buf = ci & 1;
        if (ci + 1 < 16) { stage((ci + 1) << 6, buf ^ 1); CPA_WAIT(1); }
        else { CPA_WAIT(0); }
        __syncthreads();
        uint32_t base = sb + buf * 53248u;
        uint32_t aH = base, aL = base + 9216u, bH = base + 18432u, bL = base + 35840u;
#pragma unroll
        for (int kk = 0; kk < 4; kk++) {
            uint32_t ah[4], al[4];
            uint32_t arow = (w * 16 + lr) * 144 + kk * 32 + lh * 16;
            ldsm_x4(aH + arow, ah);
            ldsm_x4(aL + arow, al);
#pragma unroll
            for (int j = 0; j < 8; j++) {
                int rowm = (kk << 4) + ((bq & 1) << 3) + br;
                int coln = (j << 4) + ((bq >> 1) << 3);
                uint32_t boff = rowm * 272 + coln * 2;
                uint32_t bh[4], bl[4];
                ldsm_x4t(bH + boff, bh);
                mma_bf16(acc[j * 2], ah, bh[0], bh[1]);
                mma_bf16(acc[j * 2 + 1], ah, bh[2], bh[3]);
                mma_bf16(acc[j * 2], al, bh[0], bh[1]);
                mma_bf16(acc[j * 2 + 1], al, bh[2], bh[3]);
                ldsm_x4t(bL + boff, bl);
                mma_bf16(acc[j * 2], ah, bl[0], bl[1]);
                mma_bf16(acc[j * 2 + 1], ah, bl[2], bl[3]);
            }
        }
        __syncthreads();
    }
    int o = (w << 4) + (lane >> 2);
#pragma unroll
    for (int f = 0; f < 16; f++) {
        int n = n0 + ((f >> 1) << 4) + ((f & 1) << 3) + ((lane & 3) << 1);
        size_t off = ((size_t)(b << 6) + o) * Nn + n;
        float2 xv = *(const float2*)&x[off];
        *(float2*)&out[off] = make_float2(acc[f].x + xv.x, acc[f].y + xv.y);
        size_t off2 = off + (size_t)8 * Nn;
        float2 xv2 = *(const float2*)&x[off2];
        *(float2*)&out[off2] = make_float2(acc[f].z + xv2.x, acc[f].w + xv2.y);
    }
}

// ---------------- launch ----------------------------------------------------
extern "C" void kernel_launch(void* const* d_in, const int* in_sizes, int n_in,
                              void* d_out, int out_size) {
    const float* x      = (const float*)d_in[0];
    const float* wphi   = (const float*)d_in[1];
    const float* wtheta = (const float*)d_in[2];
    const float* wg     = (const float*)d_in[3];
    const float* wmask  = (const float*)d_in[4];
    const float* wmv    = (const float*)d_in[5];
    const float* wmk    = (const float*)d_in[6];
    float* out = (float*)d_out;

    cudaFuncSetAttribute(k1_mma, cudaFuncAttributeMaxDynamicSharedMemorySize, 90112);
    cudaFuncSetAttribute(k2_P_mma, cudaFuncAttributeMaxDynamicSharedMemorySize, 110592);
    cudaFuncSetAttribute(k3_att_mma, cudaFuncAttributeMaxDynamicSharedMemorySize, 69632);
    cudaFuncSetAttribute(k5_gmz_mma, cudaFuncAttributeMaxDynamicSharedMemorySize, 53760);
    cudaFuncSetAttribute(k4_out_mma, cudaFuncAttributeMaxDynamicSharedMemorySize, 106496);

    k0_all<<<1024, 256>>>(wmk, wmv, wg, wphi, wtheta, wmask);
    k1_mma<<<dim3(32, 8), 256, 90112>>>(x);
    k2_P_mma<<<dim3(32, 8), 128, 110592>>>();
    k3_att_mma<<<dim3(8, 8, 32), 256, 69632>>>();
    k5_gmz_mma<<<dim3(32, 8), 256, 53760>>>();
    k4_out_mma<<<dim3(8, 32), 128, 106496>>>(x, out);
}

// round 14
// speedup vs baseline: 1.5171x; 1.5171x over previous
#include <cuda_runtime.h>
#include <cuda_bf16.h>
#include <cstdint>

#define Bq 32
#define Cc 64
#define Nn 1024

// ---------------- scratch (device globals) ----------------------------------
__device__ __nv_bfloat16 g_phiH[Bq * Cc * Nn];  // [b][c][m]
__device__ __nv_bfloat16 g_phiL[Bq * Cc * Nn];
__device__ __nv_bfloat16 g_wmkH[Nn * Nn];       // [k][m]
__device__ __nv_bfloat16 g_wmkL[Nn * Nn];
__device__ __nv_bfloat16 g_thH[Bq * Cc * Nn];   // [b][c][n] theta hi/lo
__device__ __nv_bfloat16 g_thL[Bq * Cc * Nn];
__device__ __nv_bfloat16 g_PH[Bq * Cc * Nn];    // [b][c][k] P hi/lo
__device__ __nv_bfloat16 g_PL[Bq * Cc * Nn];
__device__ float g_gm[Bq * Cc * Nn];            // [b][c][n]
__device__ __nv_bfloat16 g_EH[(size_t)Bq * Nn * Nn];  // [b][k][n] exp hi (64MB)
__device__ __nv_bfloat16 g_EL[(size_t)Bq * Nn * Nn];  // [b][k][n] exp lo (64MB)
__device__ float g_Z[Bq * Nn];
__device__ __nv_bfloat16 g_gzH[Bq * Cc * Nn];   // [b][o][m] (w_mask@gm)/Z hi/lo
__device__ __nv_bfloat16 g_gzL[Bq * Cc * Nn];
// small weight splits (filled by k0)
__device__ __nv_bfloat16 g_wphiH[Cc * Cc], g_wphiL[Cc * Cc];
__device__ __nv_bfloat16 g_wthH[Cc * Cc],  g_wthL[Cc * Cc];
__device__ __nv_bfloat16 g_wgvH[Cc * Cc],  g_wgvL[Cc * Cc];
__device__ __nv_bfloat16 g_wmaskH[Cc * Cc], g_wmaskL[Cc * Cc];

// ---------------- mma.sync / cp.async helpers -------------------------------
__device__ __forceinline__ uint32_t smem_u32(const void* p) {
    uint32_t a;
    asm("{ .reg .u64 t; cvta.to.shared.u64 t, %1; cvt.u32.u64 %0, t; }"
        : "=r"(a) : "l"(p));
    return a;
}
__device__ __forceinline__ void ldsm_x4(uint32_t addr, uint32_t r[4]) {
    asm volatile("ldmatrix.sync.aligned.m8n8.x4.shared.b16 {%0,%1,%2,%3}, [%4];"
                 : "=r"(r[0]), "=r"(r[1]), "=r"(r[2]), "=r"(r[3]) : "r"(addr));
}
__device__ __forceinline__ void ldsm_x4t(uint32_t addr, uint32_t r[4]) {
    asm volatile("ldmatrix.sync.aligned.m8n8.x4.trans.shared.b16 {%0,%1,%2,%3}, [%4];"
                 : "=r"(r[0]), "=r"(r[1]), "=r"(r[2]), "=r"(r[3]) : "r"(addr));
}
__device__ __forceinline__ void mma_bf16(float4& d, const uint32_t a[4],
                                         uint32_t b0, uint32_t b1) {
    asm volatile(
        "mma.sync.aligned.m16n8k16.row.col.f32.bf16.bf16.f32 "
        "{%0,%1,%2,%3}, {%4,%5,%6,%7}, {%8,%9}, {%0,%1,%2,%3};"
        : "+f"(d.x), "+f"(d.y), "+f"(d.z), "+f"(d.w)
        : "r"(a[0]), "r"(a[1]), "r"(a[2]), "r"(a[3]), "r"(b0), "r"(b1));
}
__device__ __forceinline__ void cpa16(uint32_t s, const void* g) {
    asm volatile("cp.async.cg.shared.global [%0], [%1], 16;" :: "r"(s), "l"(g));
}
#define CPA_COMMIT() asm volatile("cp.async.commit_group;" ::: "memory")
#define CPA_WAIT(n) asm volatile("cp.async.wait_group %0;" :: "n"(n) : "memory")

__device__ __forceinline__ uint32_t bfpack(float a, float b) {
    __nv_bfloat162 h;
    h.x = __float2bfloat16(a); h.y = __float2bfloat16(b);
    return *(uint32_t*)&h;
}
__device__ __forceinline__ void split4(float4 v, uint2& hi, uint2& lo) {
    uint32_t hA = bfpack(v.x, v.y), hB = bfpack(v.z, v.w);
    __nv_bfloat162* hp = (__nv_bfloat162*)&hA;
    __nv_bfloat162* hq = (__nv_bfloat162*)&hB;
    uint32_t lA = bfpack(v.x - __bfloat162float(hp->x), v.y - __bfloat162float(hp->y));
    uint32_t lB = bfpack(v.z - __bfloat162float(hq->x), v.w - __bfloat162float(hq->y));
    hi = make_uint2(hA, hB); lo = make_uint2(lA, lB);
}
__device__ __forceinline__ void split2(float a, float b, uint32_t& h, uint32_t& l) {
    h = bfpack(a, b);
    __nv_bfloat162* hp = (__nv_bfloat162*)&h;
    l = bfpack(a - __bfloat162float(hp->x), b - __bfloat162float(hp->y));
}

// ---------------- K0: wmk split + zero Z + small weights (merged) -----------
__global__ __launch_bounds__(256) void k0_all(
    const float* __restrict__ wmk, const float* __restrict__ wmv,
    const float* __restrict__ wg, const float* __restrict__ wphi,
    const float* __restrict__ wtheta, const float* __restrict__ wmask) {
    int t = blockIdx.x * 256 + threadIdx.x;   // 0..262143
    float4 v = ((const float4*)wmk)[t];
    uint2 hi, lo;
    split4(v, hi, lo);
    ((uint2*)g_wmkH)[t] = hi;
    ((uint2*)g_wmkL)[t] = lo;
    if (t < Bq * Nn) g_Z[t] = 0.0f;
    if (t < Cc * Cc) {
        int d = t >> 6, ci = t & 63;
        float s = 0.0f;
#pragma unroll
        for (int c = 0; c < 64; c++) s += wmv[d * 64 + c] * wg[c * 64 + ci];
        __nv_bfloat16 h;
        h = __float2bfloat16(s);
        g_wgvH[t] = h; g_wgvL[t] = __float2bfloat16(s - __bfloat162float(h));
        float u = wphi[t];
        h = __float2bfloat16(u);
        g_wphiH[t] = h; g_wphiL[t] = __float2bfloat16(u - __bfloat162float(h));
        u = wtheta[t];
        h = __float2bfloat16(u);
        g_wthH[t] = h; g_wthL[t] = __float2bfloat16(u - __bfloat162float(h));
        u = wmask[t];
        h = __float2bfloat16(u);
        g_wmaskH[t] = h; g_wmaskL[t] = __float2bfloat16(u - __bfloat162float(h));
    }
}

// ---------------- K1: channel GEMMs via mma.sync (phi, theta, gm) -----------
__global__ __launch_bounds__(256, 2) void k1_mma(const float* __restrict__ x) {
    extern __shared__ __align__(16) char sm1[];
    __nv_bfloat16* sXh = (__nv_bfloat16*)sm1;
    __nv_bfloat16* sXl = (__nv_bfloat16*)(sm1 + 17408);
    __nv_bfloat16* sW[6] = {
        (__nv_bfloat16*)(sm1 + 34816), (__nv_bfloat16*)(sm1 + 44032),
        (__nv_bfloat16*)(sm1 + 53248), (__nv_bfloat16*)(sm1 + 62464),
        (__nv_bfloat16*)(sm1 + 71680), (__nv_bfloat16*)(sm1 + 80896)};
    int b = blockIdx.x, n0 = blockIdx.y << 7;
    int t = threadIdx.x, w = t >> 5, lane = t & 31;
    int cgrp = w & 3, ngrp = w >> 2;

#pragma unroll
    for (int i = 0; i < 8; i++) {
        int lin = t + (i << 8);
        int r = lin >> 5, q = lin & 31;
        float4 v = *(const float4*)&x[((size_t)(b << 6) + r) * Nn + n0 + (q << 2)];
        uint2 hi, lo;
        split4(v, hi, lo);
        *(uint2*)&sXh[r * 136 + (q << 2)] = hi;
        *(uint2*)&sXl[r * 136 + (q << 2)] = lo;
    }
    {
        const __nv_bfloat16* src[6] = {g_wphiH, g_wphiL, g_wthH, g_wthL, g_wgvH, g_wgvL};
#pragma unroll
        for (int a = 0; a < 6; a++)
#pragma unroll
            for (int i = 0; i < 2; i++) {
                int lin = t + (i << 8);
                int r = lin >> 3, q = lin & 7;
                *(uint4*)&sW[a][r * 72 + (q << 3)] = *(const uint4*)&src[a][r * 64 + (q << 3)];
            }
    }
    __syncthreads();

    int lr = lane & 15, lh = lane >> 4;
    int bq = lane >> 3, br = lane & 7;

#pragma unroll
    for (int p = 0; p < 3; p++) {
        float4 acc[8] = {};
        __nv_bfloat16* WH = sW[p * 2];
        __nv_bfloat16* WL = sW[p * 2 + 1];
#pragma unroll
        for (int kk = 0; kk < 4; kk++) {
            uint32_t ah[4], al[4];
            ldsm_x4(smem_u32(&WH[(cgrp * 16 + lr) * 72 + kk * 16 + lh * 8]), ah);
            ldsm_x4(smem_u32(&WL[(cgrp * 16 + lr) * 72 + kk * 16 + lh * 8]), al);
#pragma unroll
            for (int j = 0; j < 4; j++) {
                int rowk = (kk << 4) + ((bq & 1) << 3) + br;
                int coln = (ngrp << 6) + (j << 4) + ((bq >> 1) << 3);
                uint32_t bh[4], bl[4];
                ldsm_x4t(smem_u32(&sXh[rowk * 136 + coln]), bh);
                mma_bf16(acc[j * 2], ah, bh[0], bh[1]);
                mma_bf16(acc[j * 2 + 1], ah, bh[2], bh[3]);
                mma_bf16(acc[j * 2], al, bh[0], bh[1]);
                mma_bf16(acc[j * 2 + 1], al, bh[2], bh[3]);
                ldsm_x4t(smem_u32(&sXl[rowk * 136 + coln]), bl);
                mma_bf16(acc[j * 2], ah, bl[0], bl[1]);
                mma_bf16(acc[j * 2 + 1], ah, bl[2], bl[3]);
            }
        }
        int m = (cgrp << 4) + (lane >> 2);
        if (p == 2) {
            float* O = g_gm + (size_t)(b << 6) * Nn;
#pragma unroll
            for (int f = 0; f < 8; f++) {
                int n = n0 + (ngrp << 6) + ((f >> 1) << 4) + ((f & 1) << 3) + ((lane & 3) << 1);
                *(float2*)&O[(size_t)m * Nn + n] = make_float2(acc[f].x, acc[f].y);
                *(float2*)&O[(size_t)(m + 8) * Nn + n] = make_float2(acc[f].z, acc[f].w);
            }
        } else {
            __nv_bfloat16* H = (p == 0 ? g_phiH : g_thH);
            __nv_bfloat16* L = (p == 0 ? g_phiL : g_thL);
            size_t rowa = ((size_t)(b << 6) + m) * Nn;
            size_t rowb2 = ((size_t)(b << 6) + m + 8) * Nn;
#pragma unroll
            for (int f = 0; f < 8; f++) {
                int n = n0 + (ngrp << 6) + ((f >> 1) << 4) + ((f & 1) << 3) + ((lane & 3) << 1);
                uint32_t h, l;
                split2(acc[f].x, acc[f].y, h, l);
                *(uint32_t*)&H[rowa + n] = h;
                *(uint32_t*)&L[rowa + n] = l;
                split2(acc[f].z, acc[f].w, h, l);
                *(uint32_t*)&H[rowb2 + n] = h;
                *(uint32_t*)&L[rowb2 + n] = l;
            }
        }
    }
}

// ---------------- K2: P = phi @ wmk^T (4 warps, 16c x 128k, cp.async) -------
// grid (32 b, 8 ktile), block 128 = 4 warps. Warp tile 16c x 128k. Chunk 64.
__global__ __launch_bounds__(128, 2) void k2_P_mma(void) {
    extern __shared__ __align__(16) char sm2[];
    uint32_t sb = smem_u32(sm2);
    int b = blockIdx.x, k0 = blockIdx.y << 7;
    int t = threadIdx.x, w = t >> 5, lane = t & 31;

    const __nv_bfloat16* Ah = g_phiH + (size_t)(b << 6) * Nn;
    const __nv_bfloat16* Al = g_phiL + (size_t)(b << 6) * Nn;

    float4 acc[16] = {};
    int lr = lane & 15, lh = lane >> 4;
    int bq = lane >> 3, br = lane & 7;

    auto stage = [&](int mc, int buf) {
        uint32_t base = sb + buf * 55296u;
        uint32_t aH = base, aL = base + 9216u, bH = base + 18432u, bL = base + 36864u;
#pragma unroll
        for (int i = 0; i < 4; i++) {
            int lin = t + (i << 7);
            int r = lin >> 3, q = lin & 7;
            cpa16(aH + r * 144 + (q << 4), &Ah[(size_t)r * Nn + mc + (q << 3)]);
            cpa16(aL + r * 144 + (q << 4), &Al[(size_t)r * Nn + mc + (q << 3)]);
        }
#pragma unroll
        for (int i = 0; i < 8; i++) {
            int lin = t + (i << 7);
            int r = lin >> 3, q = lin & 7;
            cpa16(bH + r * 144 + (q << 4), &g_wmkH[(size_t)(k0 + r) * Nn + mc + (q << 3)]);
            cpa16(bL + r * 144 + (q << 4), &g_wmkL[(size_t)(k0 + r) * Nn + mc + (q << 3)]);
        }
        CPA_COMMIT();
    };

    stage(0, 0);
    for (int ci = 0; ci < 16; ci++) {
        int buf = ci & 1;
        if (ci + 1 < 16) { stage((ci + 1) << 6, buf ^ 1); CPA_WAIT(1); }
        else { CPA_WAIT(0); }
        __syncthreads();
        uint32_t base = sb + buf * 55296u;
        uint32_t aH = base, aL = base + 9216u, bH = base + 18432u, bL = base + 36864u;
#pragma unroll
        for (int kk = 0; kk < 4; kk++) {
            uint32_t ah[4], al[4];
            uint32_t arow = (w * 16 + lr) * 144 + kk * 32 + lh * 16;
            ldsm_x4(aH + arow, ah);
            ldsm_x4(aL + arow, al);
#pragma unroll
            for (int j = 0; j < 8; j++) {
                int rowb = (j << 4) + ((bq >> 1) << 3) + br;
                uint32_t boff = rowb * 144 + kk * 32 + ((bq & 1) << 4);
                uint32_t bh[4], bl[4];
                ldsm_x4(bH + boff, bh);
                mma_bf16(acc[j * 2], ah, bh[0], bh[1]);
                mma_bf16(acc[j * 2 + 1], ah, bh[2], bh[3]);
                mma_bf16(acc[j * 2], al, bh[0], bh[1]);
                mma_bf16(acc[j * 2 + 1], al, bh[2], bh[3]);
                ldsm_x4(bL + boff, bl);
                mma_bf16(acc[j * 2], ah, bl[0], bl[1]);
                mma_bf16(acc[j * 2 + 1], ah, bl[2], bl[3]);
            }
        }
        __syncthreads();
    }

    int m = (w << 4) + (lane >> 2);
    size_t prow = ((size_t)(b << 6) + m) * Nn + k0;
#pragma unroll
    for (int f = 0; f < 16; f++) {
        int n = ((f >> 1) << 4) + ((f & 1) << 3) + ((lane & 3) << 1);
        uint32_t h, l;
        split2(acc[f].x, acc[f].y, h, l);
        *(uint32_t*)&g_PH[prow + n] = h;
        *(uint32_t*)&g_PL[prow + n] = l;
        split2(acc[f].z, acc[f].w, h, l);
        *(uint32_t*)&g_PH[prow + 8 * Nn + n] = h;
        *(uint32_t*)&g_PL[prow + 8 * Nn + n] = l;
    }
}

// ---------------- K3: Et = exp(P^T theta), smem epilogue (R10 grid order) ---
// grid (8 ktile, 8 ntile, 32 b), block 256. CTA tile 128k x 128n, c = 64.
__global__ __launch_bounds__(256, 2) void k3_att_mma(void) {
    extern __shared__ __align__(16) char sm3[];
    __nv_bfloat16* sPh = (__nv_bfloat16*)sm3;              // [64][136]
    __nv_bfloat16* sPl = (__nv_bfloat16*)(sm3 + 17408);
    __nv_bfloat16* sTh = (__nv_bfloat16*)(sm3 + 34816);
    __nv_bfloat16* sTl = (__nv_bfloat16*)(sm3 + 52224);
    int b = blockIdx.z, k0 = blockIdx.x << 7, n0 = blockIdx.y << 7;
    int t = threadIdx.x, w = t >> 5, lane = t & 31;
    int kw = w & 3, nw = w >> 2;

#pragma unroll
    for (int i = 0; i < 4; i++) {
        int lin = t + (i << 8);
        int r = lin >> 4, q = lin & 15;
        size_t pofs = ((size_t)(b << 6) + r) * Nn + k0 + (q << 3);
        size_t tofs = ((size_t)(b << 6) + r) * Nn + n0 + (q << 3);
        *(uint4*)&sPh[r * 136 + (q << 3)] = *(const uint4*)&g_PH[pofs];
        *(uint4*)&sPl[r * 136 + (q << 3)] = *(const uint4*)&g_PL[pofs];
        *(uint4*)&sTh[r * 136 + (q << 3)] = *(const uint4*)&g_thH[tofs];
        *(uint4*)&sTl[r * 136 + (q << 3)] = *(const uint4*)&g_thL[tofs];
    }
    __syncthreads();

    float4 acc[2][8] = {};
    int bq = lane >> 3, br = lane & 7;
#pragma unroll
    for (int kk = 0; kk < 4; kk++) {
        int c0 = kk << 4;
        uint32_t ah[2][4], al[2][4];
#pragma unroll
        for (int mt = 0; mt < 2; mt++) {
            int m0 = (kw << 5) + (mt << 4);
            int rowc = c0 + ((bq >> 1) << 3) + br;
            int colm = m0 + ((bq & 1) << 3);
            ldsm_x4t(smem_u32(&sPh[rowc * 136 + colm]), ah[mt]);
            ldsm_x4t(smem_u32(&sPl[rowc * 136 + colm]), al[mt]);
        }
#pragma unroll
        for (int j = 0; j < 4; j++) {
            int rowc = c0 + ((bq & 1) << 3) + br;
            int coln = (nw << 6) + (j << 4) + ((bq >> 1) << 3);
            uint32_t bh[4], bl[4];
            ldsm_x4t(smem_u32(&sTh[rowc * 136 + coln]), bh);
            ldsm_x4t(smem_u32(&sTl[rowc * 136 + coln]), bl);
#pragma unroll
            for (int mt = 0; mt < 2; mt++) {
                mma_bf16(acc[mt][j * 2], ah[mt], bh[0], bh[1]);
                mma_bf16(acc[mt][j * 2 + 1], ah[mt], bh[2], bh[3]);
                mma_bf16(acc[mt][j * 2], al[mt], bh[0], bh[1]);
                mma_bf16(acc[mt][j * 2 + 1], al[mt], bh[2], bh[3]);
                mma_bf16(acc[mt][j * 2], ah[mt], bl[0], bl[1]);
                mma_bf16(acc[mt][j * 2 + 1], ah[mt], bl[2], bl[3]);
            }
        }
    }

    __syncthreads();
    __nv_bfloat16* sEH = (__nv_bfloat16*)sm3;
    __nv_bfloat16* sEL = (__nv_bfloat16*)(sm3 + 34816);
#pragma unroll
    for (int mt = 0; mt < 2; mt++) {
        int krow = (kw << 5) + (mt << 4) + (lane >> 2);
        float sA = 0.f, sB = 0.f;
#pragma unroll
        for (int j = 0; j < 8; j++) {
            int nc = (nw << 6) + (j << 3) + ((lane & 3) << 1);
            float ex = __expf(acc[mt][j].x), ey = __expf(acc[mt][j].y);
            float ez = __expf(acc[mt][j].z), ew = __expf(acc[mt][j].w);
            sA += ex + ey; sB += ez + ew;
            uint32_t h0, l0, h1, l1;
            split2(ex, ey, h0, l0);
            split2(ez, ew, h1, l1);
            *(uint32_t*)&sEH[krow * 136 + nc] = h0;
            *(uint32_t*)&sEL[krow * 136 + nc] = l0;
            *(uint32_t*)&sEH[(krow + 8) * 136 + nc] = h1;
            *(uint32_t*)&sEL[(krow + 8) * 136 + nc] = l1;
        }
        sA += __shfl_xor_sync(0xffffffffu, sA, 1);
        sA += __shfl_xor_sync(0xffffffffu, sA, 2);
        sB += __shfl_xor_sync(0xffffffffu, sB, 1);
        sB += __shfl_xor_sync(0xffffffffu, sB, 2);
        if ((lane & 3) == 0) {
            atomicAdd(&g_Z[b * Nn + k0 + krow], sA);
            atomicAdd(&g_Z[b * Nn + k0 + krow + 8], sB);
        }
    }
    __syncthreads();
#pragma unroll
    for (int i = 0; i < 8; i++) {
        int lin = t + (i << 8);
        int r = lin >> 4, q = lin & 15;
        size_t off = ((size_t)(b * Nn + k0 + r)) * Nn + n0 + (q << 3);
        *(uint4*)&g_EH[off] = *(uint4*)&sEH[r * 136 + (q << 3)];
        *(uint4*)&g_EL[off] = *(uint4*)&sEL[r * 136 + (q << 3)];
    }
}

// ---------------- K5: gz = (wmask@gm)/Z via mma.sync, bf16 hi/lo out --------
__global__ __launch_bounds__(256, 2) void k5_gmz_mma(void) {
    extern __shared__ __align__(16) char sm5[];
    __nv_bfloat16* sGh = (__nv_bfloat16*)sm5;
    __nv_bfloat16* sGl = (__nv_bfloat16*)(sm5 + 17408);
    __nv_bfloat16* sWh = (__nv_bfloat16*)(sm5 + 34816);
    __nv_bfloat16* sWl = (__nv_bfloat16*)(sm5 + 44032);
    float* szm = (float*)(sm5 + 53248);
    int b = blockIdx.x, m0 = blockIdx.y << 7;
    int t = threadIdx.x, w = t >> 5, lane = t & 31;
    int ogrp = w & 3, mgrp = w >> 2;

    const float* gm = g_gm + (size_t)(b << 6) * Nn;
#pragma unroll
    for (int i = 0; i < 8; i++) {
        int lin = t + (i << 8);
        int r = lin >> 5, q = lin & 31;
        float4 v = *(const float4*)&gm[(size_t)r * Nn + m0 + (q << 2)];
        uint2 hi, lo;
        split4(v, hi, lo);
        *(uint2*)&sGh[r * 136 + (q << 2)] = hi;
        *(uint2*)&sGl[r * 136 + (q << 2)] = lo;
    }
#pragma unroll
    for (int i = 0; i < 2; i++) {
        int lin = t + (i << 8);
        int r = lin >> 3, q = lin & 7;
        *(uint4*)&sWh[r * 72 + (q << 3)] = *(const uint4*)&g_wmaskH[r * 64 + (q << 3)];
        *(uint4*)&sWl[r * 72 + (q << 3)] = *(const uint4*)&g_wmaskL[r * 64 + (q << 3)];
    }
    if (t < 128) szm[t] = 1.0f / g_Z[b * Nn + m0 + t];
    __syncthreads();

    int lr = lane & 15, lh = lane >> 4;
    int bq = lane >> 3, br = lane & 7;

    float4 acc[8] = {};
#pragma unroll
    for (int kk = 0; kk < 4; kk++) {
        uint32_t ah[4], al[4];
        ldsm_x4(smem_u32(&sWh[(ogrp * 16 + lr) * 72 + kk * 16 + lh * 8]), ah);
        ldsm_x4(smem_u32(&sWl[(ogrp * 16 + lr) * 72 + kk * 16 + lh * 8]), al);
#pragma unroll
        for (int j = 0; j < 4; j++) {
            int rowk = (kk << 4) + ((bq & 1) << 3) + br;
            int colm = (mgrp << 6) + (j << 4) + ((bq >> 1) << 3);
            uint32_t bh[4], bl[4];
            ldsm_x4t(smem_u32(&sGh[rowk * 136 + colm]), bh);
            mma_bf16(acc[j * 2], ah, bh[0], bh[1]);
            mma_bf16(acc[j * 2 + 1], ah, bh[2], bh[3]);
            mma_bf16(acc[j * 2], al, bh[0], bh[1]);
            mma_bf16(acc[j * 2 + 1], al, bh[2], bh[3]);
            ldsm_x4t(smem_u32(&sGl[rowk * 136 + colm]), bl);
            mma_bf16(acc[j * 2], ah, bl[0], bl[1]);
            mma_bf16(acc[j * 2 + 1], ah, bl[2], bl[3]);
        }
    }
    int o = (ogrp << 4) + (lane >> 2);
    size_t rowa = ((size_t)(b << 6) + o) * Nn + m0;
    size_t rowb2 = ((size_t)(b << 6) + o + 8) * Nn + m0;
#pragma unroll
    for (int f = 0; f < 8; f++) {
        int mm = (mgrp << 6) + ((f >> 1) << 4) + ((f & 1) << 3) + ((lane & 3) << 1);
        float i0 = szm[mm], i1 = szm[mm + 1];
        uint32_t h, l;
        split2(acc[f].x * i0, acc[f].y * i1, h, l);
        *(uint32_t*)&g_gzH[rowa + mm] = h;
        *(uint32_t*)&g_gzL[rowa + mm] = l;
        split2(acc[f].z * i0, acc[f].w * i1, h, l);
        *(uint32_t*)&g_gzH[rowb2 + mm] = h;
        *(uint32_t*)&g_gzL[rowb2 + mm] = l;
    }
}

// ---------------- K4: out = gz @ E + x (R10 config: 4 warps, b-fastest grid)
__global__ __launch_bounds__(128, 2) void k4_out_mma(
    const float* __restrict__ x, float* __restrict__ out) {
    extern __shared__ __align__(16) char sm4[];
    uint32_t sb = smem_u32(sm4);
    int b = blockIdx.x, n0 = blockIdx.y << 7;
    int t = threadIdx.x, w = t >> 5, lane = t & 31;

    float4 acc[16] = {};
    int lr = lane & 15, lh = lane >> 4;
    int bq = lane >> 3, br = lane & 7;

    auto stage = [&](int mc, int buf) {
        uint32_t base = sb + buf * 53248u;
        uint32_t aH = base, aL = base + 9216u, bH = base + 18432u, bL = base + 35840u;
#pragma unroll
        for (int i = 0; i < 4; i++) {
            int lin = t + (i << 7);
            int r = lin >> 3, q = lin & 7;
            size_t gofs = ((size_t)(b << 6) + r) * Nn + mc + (q << 3);
            cpa16(aH + r * 144 + (q << 4), &g_gzH[gofs]);
            cpa16(aL + r * 144 + (q << 4), &g_gzL[gofs]);
        }
#pragma unroll
        for (int i = 0; i < 8; i++) {
            int lin = t + (i << 7);
            int r = lin >> 4, q = lin & 15;
            size_t off = ((size_t)(b * Nn) + mc + r) * Nn + n0 + (q << 3);
            cpa16(bH + r * 272 + (q << 4), &g_EH[off]);
            cpa16(bL + r * 272 + (q << 4), &g_EL[off]);
        }
        CPA_COMMIT();
    };

    stage(0, 0);
    for (int ci = 0; ci < 16; ci++) {
        int buf = ci & 1;
        if (ci + 1 < 16) { stage((ci + 1) << 6, buf ^ 1); CPA_WAIT(1); }
        else { CPA_WAIT(0); }
        __syncthreads();
        uint32_t base = sb + buf * 53248u;
        uint32_t aH = base, aL = base + 9216u, bH = base + 18432u, bL = base + 35840u;
#pragma unroll
        for (int kk = 0; kk < 4; kk++) {
            uint32_t ah[4], al[4];
            uint32_t arow = (w * 16 + lr) * 144 + kk * 32 + lh * 16;
            ldsm_x4(aH + arow, ah);
            ldsm_x4(aL + arow, al);
#pragma unroll
            for (int j = 0; j < 8; j++) {
                int rowm = (kk << 4) + ((bq & 1) << 3) + br;
                int coln = (j << 4) + ((bq >> 1) << 3);
                uint32_t boff = rowm * 272 + coln * 2;
                uint32_t bh[4], bl[4];
                ldsm_x4t(bH + boff, bh);
                mma_bf16(acc[j * 2], ah, bh[0], bh[1]);
                mma_bf16(acc[j * 2 + 1], ah, bh[2], bh[3]);
                mma_bf16(acc[j * 2], al, bh[0], bh[1]);
                mma_bf16(acc[j * 2 + 1], al, bh[2], bh[3]);
                ldsm_x4t(bL + boff, bl);
                mma_bf16(acc[j * 2], ah, bl[0], bl[1]);
                mma_bf16(acc[j * 2 + 1], ah, bl[2], bl[3]);
            }
        }
        __syncthreads();
    }
    int o = (w << 4) + (lane >> 2);
#pragma unroll
    for (int f = 0; f < 16; f++) {
        int n = n0 + ((f >> 1) << 4) + ((f & 1) << 3) + ((lane & 3) << 1);
        size_t off = ((size_t)(b << 6) + o) * Nn + n;
        float2 xv = *(const float2*)&x[off];
        *(float2*)&out[off] = make_float2(acc[f].x + xv.x, acc[f].y + xv.y);
        size_t off2 = off + (size_t)8 * Nn;
        float2 xv2 = *(const float2*)&x[off2];
        *(float2*)&out[off2] = make_float2(acc[f].z + xv2.x, acc[f].w + xv2.y);
    }
}

// ---------------- launch ----------------------------------------------------
extern "C" void kernel_launch(void* const* d_in, const int* in_sizes, int n_in,
                              void* d_out, int out_size) {
    const float* x      = (const float*)d_in[0];
    const float* wphi   = (const float*)d_in[1];
    const float* wtheta = (const float*)d_in[2];
    const float* wg     = (const float*)d_in[3];
    const float* wmask  = (const float*)d_in[4];
    const float* wmv    = (const float*)d_in[5];
    const float* wmk    = (const float*)d_in[6];
    float* out = (float*)d_out;

    cudaFuncSetAttribute(k1_mma, cudaFuncAttributeMaxDynamicSharedMemorySize, 90112);
    cudaFuncSetAttribute(k2_P_mma, cudaFuncAttributeMaxDynamicSharedMemorySize, 110592);
    cudaFuncSetAttribute(k3_att_mma, cudaFuncAttributeMaxDynamicSharedMemorySize, 69632);
    cudaFuncSetAttribute(k5_gmz_mma, cudaFuncAttributeMaxDynamicSharedMemorySize, 53760);
    cudaFuncSetAttribute(k4_out_mma, cudaFuncAttributeMaxDynamicSharedMemorySize, 106496);

    k0_all<<<1024, 256>>>(wmk, wmv, wg, wphi, wtheta, wmask);
    k1_mma<<<dim3(32, 8), 256, 90112>>>(x);
    k2_P_mma<<<dim3(32, 8), 128, 110592>>>();
    k3_att_mma<<<dim3(8, 8, 32), 256, 69632>>>();
    k5_gmz_mma<<<dim3(32, 8), 256, 53760>>>();
    k4_out_mma<<<dim3(32, 8), 128, 106496>>>(x, out);
}

// round 15
// speedup vs baseline: 1.5403x; 1.0153x over previous
#include <cuda_runtime.h>
#include <cuda_bf16.h>
#include <cstdint>

#define Bq 32
#define Cc 64
#define Nn 1024

// ---------------- scratch (device globals) ----------------------------------
__device__ __nv_bfloat16 g_phiH[Bq * Cc * Nn];  // [b][c][m]
__device__ __nv_bfloat16 g_phiL[Bq * Cc * Nn];
__device__ __nv_bfloat16 g_wmkH[Nn * Nn];       // [k][m]
__device__ __nv_bfloat16 g_wmkL[Nn * Nn];
__device__ __nv_bfloat16 g_thH[Bq * Cc * Nn];   // [b][c][n] theta hi/lo
__device__ __nv_bfloat16 g_thL[Bq * Cc * Nn];
__device__ __nv_bfloat16 g_PH[Bq * Cc * Nn];    // [b][c][k] P hi/lo
__device__ __nv_bfloat16 g_PL[Bq * Cc * Nn];
__device__ float g_gm[Bq * Cc * Nn];            // [b][c][n]
__device__ __nv_bfloat16 g_EH[(size_t)Bq * Nn * Nn];  // [b][k][n] exp hi (64MB)
__device__ __nv_bfloat16 g_EL[(size_t)Bq * Nn * Nn];  // [b][k][n] exp lo (64MB)
__device__ float g_Z[Bq * Nn];
__device__ __nv_bfloat16 g_gzH[Bq * Cc * Nn];   // [b][o][m] (w_mask@gm)/Z hi/lo
__device__ __nv_bfloat16 g_gzL[Bq * Cc * Nn];
// small weight splits (filled by k0)
__device__ __nv_bfloat16 g_wphiH[Cc * Cc], g_wphiL[Cc * Cc];
__device__ __nv_bfloat16 g_wthH[Cc * Cc],  g_wthL[Cc * Cc];
__device__ __nv_bfloat16 g_wgvH[Cc * Cc],  g_wgvL[Cc * Cc];
__device__ __nv_bfloat16 g_wmaskH[Cc * Cc], g_wmaskL[Cc * Cc];

// ---------------- mma.sync / cp.async helpers -------------------------------
__device__ __forceinline__ uint32_t smem_u32(const void* p) {
    uint32_t a;
    asm("{ .reg .u64 t; cvta.to.shared.u64 t, %1; cvt.u32.u64 %0, t; }"
        : "=r"(a) : "l"(p));
    return a;
}
__device__ __forceinline__ void ldsm_x4(uint32_t addr, uint32_t r[4]) {
    asm volatile("ldmatrix.sync.aligned.m8n8.x4.shared.b16 {%0,%1,%2,%3}, [%4];"
                 : "=r"(r[0]), "=r"(r[1]), "=r"(r[2]), "=r"(r[3]) : "r"(addr));
}
__device__ __forceinline__ void ldsm_x4t(uint32_t addr, uint32_t r[4]) {
    asm volatile("ldmatrix.sync.aligned.m8n8.x4.trans.shared.b16 {%0,%1,%2,%3}, [%4];"
                 : "=r"(r[0]), "=r"(r[1]), "=r"(r[2]), "=r"(r[3]) : "r"(addr));
}
__device__ __forceinline__ void mma_bf16(float4& d, const uint32_t a[4],
                                         uint32_t b0, uint32_t b1) {
    asm volatile(
        "mma.sync.aligned.m16n8k16.row.col.f32.bf16.bf16.f32 "
        "{%0,%1,%2,%3}, {%4,%5,%6,%7}, {%8,%9}, {%0,%1,%2,%3};"
        : "+f"(d.x), "+f"(d.y), "+f"(d.z), "+f"(d.w)
        : "r"(a[0]), "r"(a[1]), "r"(a[2]), "r"(a[3]), "r"(b0), "r"(b1));
}
__device__ __forceinline__ void cpa16(uint32_t s, const void* g) {
    asm volatile("cp.async.cg.shared.global [%0], [%1], 16;" :: "r"(s), "l"(g));
}
#define CPA_COMMIT() asm volatile("cp.async.commit_group;" ::: "memory")
#define CPA_WAIT(n) asm volatile("cp.async.wait_group %0;" :: "n"(n) : "memory")

// packed f32x2 -> bf16x2 convert (one instruction; lo = a, hi = b, round rn)
__device__ __forceinline__ uint32_t cvt2(float a, float b) {
    uint32_t r;
    asm("cvt.rn.bf16x2.f32 %0, %1, %2;" : "=r"(r) : "f"(b), "f"(a));
    return r;
}
// hi/lo split: bit-identical to scalar __float2bfloat16 path, fewer instrs
__device__ __forceinline__ void split2(float a, float b, uint32_t& h, uint32_t& l) {
    h = cvt2(a, b);
    float ha = __uint_as_float(h << 16);
    float hb = __uint_as_float(h & 0xffff0000u);
    l = cvt2(a - ha, b - hb);
}
__device__ __forceinline__ void split4(float4 v, uint2& hi, uint2& lo) {
    uint32_t h0, l0, h1, l1;
    split2(v.x, v.y, h0, l0);
    split2(v.z, v.w, h1, l1);
    hi = make_uint2(h0, h1); lo = make_uint2(l0, l1);
}

// ---------------- K0: wmk split + zero Z + small weights (merged) -----------
__global__ __launch_bounds__(256) void k0_all(
    const float* __restrict__ wmk, const float* __restrict__ wmv,
    const float* __restrict__ wg, const float* __restrict__ wphi,
    const float* __restrict__ wtheta, const float* __restrict__ wmask) {
    int t = blockIdx.x * 256 + threadIdx.x;   // 0..262143
    float4 v = ((const float4*)wmk)[t];
    uint2 hi, lo;
    split4(v, hi, lo);
    ((uint2*)g_wmkH)[t] = hi;
    ((uint2*)g_wmkL)[t] = lo;
    if (t < Bq * Nn) g_Z[t] = 0.0f;
    if (t < Cc * Cc) {
        int d = t >> 6, ci = t & 63;
        float s = 0.0f;
#pragma unroll
        for (int c = 0; c < 64; c++) s += wmv[d * 64 + c] * wg[c * 64 + ci];
        uint32_t h, l;
        split2(s, 0.0f, h, l);
        g_wgvH[t] = __ushort_as_bfloat16((unsigned short)(h & 0xffff));
        g_wgvL[t] = __ushort_as_bfloat16((unsigned short)(l & 0xffff));
        split2(wphi[t], 0.0f, h, l);
        g_wphiH[t] = __ushort_as_bfloat16((unsigned short)(h & 0xffff));
        g_wphiL[t] = __ushort_as_bfloat16((unsigned short)(l & 0xffff));
        split2(wtheta[t], 0.0f, h, l);
        g_wthH[t] = __ushort_as_bfloat16((unsigned short)(h & 0xffff));
        g_wthL[t] = __ushort_as_bfloat16((unsigned short)(l & 0xffff));
        split2(wmask[t], 0.0f, h, l);
        g_wmaskH[t] = __ushort_as_bfloat16((unsigned short)(h & 0xffff));
        g_wmaskL[t] = __ushort_as_bfloat16((unsigned short)(l & 0xffff));
    }
}

// ---------------- K1: channel GEMMs via mma.sync (phi, theta, gm) -----------
__global__ __launch_bounds__(256, 2) void k1_mma(const float* __restrict__ x) {
    extern __shared__ __align__(16) char sm1[];
    __nv_bfloat16* sXh = (__nv_bfloat16*)sm1;
    __nv_bfloat16* sXl = (__nv_bfloat16*)(sm1 + 17408);
    __nv_bfloat16* sW[6] = {
        (__nv_bfloat16*)(sm1 + 34816), (__nv_bfloat16*)(sm1 + 44032),
        (__nv_bfloat16*)(sm1 + 53248), (__nv_bfloat16*)(sm1 + 62464),
        (__nv_bfloat16*)(sm1 + 71680), (__nv_bfloat16*)(sm1 + 80896)};
    int b = blockIdx.x, n0 = blockIdx.y << 7;
    int t = threadIdx.x, w = t >> 5, lane = t & 31;
    int cgrp = w & 3, ngrp = w >> 2;

#pragma unroll
    for (int i = 0; i < 8; i++) {
        int lin = t + (i << 8);
        int r = lin >> 5, q = lin & 31;
        float4 v = *(const float4*)&x[((size_t)(b << 6) + r) * Nn + n0 + (q << 2)];
        uint2 hi, lo;
        split4(v, hi, lo);
        *(uint2*)&sXh[r * 136 + (q << 2)] = hi;
        *(uint2*)&sXl[r * 136 + (q << 2)] = lo;
    }
    {
        const __nv_bfloat16* src[6] = {g_wphiH, g_wphiL, g_wthH, g_wthL, g_wgvH, g_wgvL};
#pragma unroll
        for (int a = 0; a < 6; a++)
#pragma unroll
            for (int i = 0; i < 2; i++) {
                int lin = t + (i << 8);
                int r = lin >> 3, q = lin & 7;
                *(uint4*)&sW[a][r * 72 + (q << 3)] = *(const uint4*)&src[a][r * 64 + (q << 3)];
            }
    }
    __syncthreads();

    int lr = lane & 15, lh = lane >> 4;
    int bq = lane >> 3, br = lane & 7;

#pragma unroll
    for (int p = 0; p < 3; p++) {
        float4 acc[8] = {};
        __nv_bfloat16* WH = sW[p * 2];
        __nv_bfloat16* WL = sW[p * 2 + 1];
#pragma unroll
        for (int kk = 0; kk < 4; kk++) {
            uint32_t ah[4], al[4];
            ldsm_x4(smem_u32(&WH[(cgrp * 16 + lr) * 72 + kk * 16 + lh * 8]), ah);
            ldsm_x4(smem_u32(&WL[(cgrp * 16 + lr) * 72 + kk * 16 + lh * 8]), al);
#pragma unroll
            for (int j = 0; j < 4; j++) {
                int rowk = (kk << 4) + ((bq & 1) << 3) + br;
                int coln = (ngrp << 6) + (j << 4) + ((bq >> 1) << 3);
                uint32_t bh[4], bl[4];
                ldsm_x4t(smem_u32(&sXh[rowk * 136 + coln]), bh);
                mma_bf16(acc[j * 2], ah, bh[0], bh[1]);
                mma_bf16(acc[j * 2 + 1], ah, bh[2], bh[3]);
                mma_bf16(acc[j * 2], al, bh[0], bh[1]);
                mma_bf16(acc[j * 2 + 1], al, bh[2], bh[3]);
                ldsm_x4t(smem_u32(&sXl[rowk * 136 + coln]), bl);
                mma_bf16(acc[j * 2], ah, bl[0], bl[1]);
                mma_bf16(acc[j * 2 + 1], ah, bl[2], bl[3]);
            }
        }
        int m = (cgrp << 4) + (lane >> 2);
        if (p == 2) {
            float* O = g_gm + (size_t)(b << 6) * Nn;
#pragma unroll
            for (int f = 0; f < 8; f++) {
                int n = n0 + (ngrp << 6) + ((f >> 1) << 4) + ((f & 1) << 3) + ((lane & 3) << 1);
                *(float2*)&O[(size_t)m * Nn + n] = make_float2(acc[f].x, acc[f].y);
                *(float2*)&O[(size_t)(m + 8) * Nn + n] = make_float2(acc[f].z, acc[f].w);
            }
        } else {
            __nv_bfloat16* H = (p == 0 ? g_phiH : g_thH);
            __nv_bfloat16* L = (p == 0 ? g_phiL : g_thL);
            size_t rowa = ((size_t)(b << 6) + m) * Nn;
            size_t rowb2 = ((size_t)(b << 6) + m + 8) * Nn;
#pragma unroll
            for (int f = 0; f < 8; f++) {
                int n = n0 + (ngrp << 6) + ((f >> 1) << 4) + ((f & 1) << 3) + ((lane & 3) << 1);
                uint32_t h, l;
                split2(acc[f].x, acc[f].y, h, l);
                *(uint32_t*)&H[rowa + n] = h;
                *(uint32_t*)&L[rowa + n] = l;
                split2(acc[f].z, acc[f].w, h, l);
                *(uint32_t*)&H[rowb2 + n] = h;
                *(uint32_t*)&L[rowb2 + n] = l;
            }
        }
    }
}

// ---------------- K2: P = phi @ wmk^T (4 warps, 16c x 128k, cp.async) -------
__global__ __launch_bounds__(128, 2) void k2_P_mma(void) {
    extern __shared__ __align__(16) char sm2[];
    uint32_t sb = smem_u32(sm2);
    int b = blockIdx.x, k0 = blockIdx.y << 7;
    int t = threadIdx.x, w = t >> 5, lane = t & 31;

    const __nv_bfloat16* Ah = g_phiH + (size_t)(b << 6) * Nn;
    const __nv_bfloat16* Al = g_phiL + (size_t)(b << 6) * Nn;

    float4 acc[16] = {};
    int lr = lane & 15, lh = lane >> 4;
    int bq = lane >> 3, br = lane & 7;

    auto stage = [&](int mc, int buf) {
        uint32_t base = sb + buf * 55296u;
        uint32_t aH = base, aL = base + 9216u, bH = base + 18432u, bL = base + 36864u;
#pragma unroll
        for (int i = 0; i < 4; i++) {
            int lin = t + (i << 7);
            int r = lin >> 3, q = lin & 7;
            cpa16(aH + r * 144 + (q << 4), &Ah[(size_t)r * Nn + mc + (q << 3)]);
            cpa16(aL + r * 144 + (q << 4), &Al[(size_t)r * Nn + mc + (q << 3)]);
        }
#pragma unroll
        for (int i = 0; i < 8; i++) {
            int lin = t + (i << 7);
            int r = lin >> 3, q = lin & 7;
            cpa16(bH + r * 144 + (q << 4), &g_wmkH[(size_t)(k0 + r) * Nn + mc + (q << 3)]);
            cpa16(bL + r * 144 + (q << 4), &g_wmkL[(size_t)(k0 + r) * Nn + mc + (q << 3)]);
        }
        CPA_COMMIT();
    };

    stage(0, 0);
    for (int ci = 0; ci < 16; ci++) {
        int buf = ci & 1;
        if (ci + 1 < 16) { stage((ci + 1) << 6, buf ^ 1); CPA_WAIT(1); }
        else { CPA_WAIT(0); }
        __syncthreads();
        uint32_t base = sb + buf * 55296u;
        uint32_t aH = base, aL = base + 9216u, bH = base + 18432u, bL = base + 36864u;
#pragma unroll
        for (int kk = 0; kk < 4; kk++) {
            uint32_t ah[4], al[4];
            uint32_t arow = (w * 16 + lr) * 144 + kk * 32 + lh * 16;
            ldsm_x4(aH + arow, ah);
            ldsm_x4(aL + arow, al);
#pragma unroll
            for (int j = 0; j < 8; j++) {
                int rowb = (j << 4) + ((bq >> 1) << 3) + br;
                uint32_t boff = rowb * 144 + kk * 32 + ((bq & 1) << 4);
                uint32_t bh[4], bl[4];
                ldsm_x4(bH + boff, bh);
                mma_bf16(acc[j * 2], ah, bh[0], bh[1]);
                mma_bf16(acc[j * 2 + 1], ah, bh[2], bh[3]);
                mma_bf16(acc[j * 2], al, bh[0], bh[1]);
                mma_bf16(acc[j * 2 + 1], al, bh[2], bh[3]);
                ldsm_x4(bL + boff, bl);
                mma_bf16(acc[j * 2], ah, bl[0], bl[1]);
                mma_bf16(acc[j * 2 + 1], ah, bl[2], bl[3]);
            }
        }
        __syncthreads();
    }

    int m = (w << 4) + (lane >> 2);
    size_t prow = ((size_t)(b << 6) + m) * Nn + k0;
#pragma unroll
    for (int f = 0; f < 16; f++) {
        int n = ((f >> 1) << 4) + ((f & 1) << 3) + ((lane & 3) << 1);
        uint32_t h, l;
        split2(acc[f].x, acc[f].y, h, l);
        *(uint32_t*)&g_PH[prow + n] = h;
        *(uint32_t*)&g_PL[prow + n] = l;
        split2(acc[f].z, acc[f].w, h, l);
        *(uint32_t*)&g_PH[prow + 8 * Nn + n] = h;
        *(uint32_t*)&g_PL[prow + 8 * Nn + n] = l;
    }
}

// ---------------- K3: Et = exp(P^T theta), smem epilogue, cp.async stage ----
// grid (8 ktile, 8 ntile, 32 b), block 256. CTA tile 128k x 128n, c = 64.
__global__ __launch_bounds__(256, 2) void k3_att_mma(void) {
    extern __shared__ __align__(16) char sm3[];
    __nv_bfloat16* sPh = (__nv_bfloat16*)sm3;              // [64][136]
    __nv_bfloat16* sPl = (__nv_bfloat16*)(sm3 + 17408);
    __nv_bfloat16* sTh = (__nv_bfloat16*)(sm3 + 34816);
    __nv_bfloat16* sTl = (__nv_bfloat16*)(sm3 + 52224);
    int b = blockIdx.z, k0 = blockIdx.x << 7, n0 = blockIdx.y << 7;
    int t = threadIdx.x, w = t >> 5, lane = t & 31;
    int kw = w & 3, nw = w >> 2;

#pragma unroll
    for (int i = 0; i < 4; i++) {
        int lin = t + (i << 8);
        int r = lin >> 4, q = lin & 15;
        size_t pofs = ((size_t)(b << 6) + r) * Nn + k0 + (q << 3);
        size_t tofs = ((size_t)(b << 6) + r) * Nn + n0 + (q << 3);
        cpa16(smem_u32(&sPh[r * 136 + (q << 3)]), &g_PH[pofs]);
        cpa16(smem_u32(&sPl[r * 136 + (q << 3)]), &g_PL[pofs]);
        cpa16(smem_u32(&sTh[r * 136 + (q << 3)]), &g_thH[tofs]);
        cpa16(smem_u32(&sTl[r * 136 + (q << 3)]), &g_thL[tofs]);
    }
    CPA_COMMIT(); CPA_WAIT(0);
    __syncthreads();

    float4 acc[2][8] = {};
    int bq = lane >> 3, br = lane & 7;
#pragma unroll
    for (int kk = 0; kk < 4; kk++) {
        int c0 = kk << 4;
        uint32_t ah[2][4], al[2][4];
#pragma unroll
        for (int mt = 0; mt < 2; mt++) {
            int m0 = (kw << 5) + (mt << 4);
            int rowc = c0 + ((bq >> 1) << 3) + br;
            int colm = m0 + ((bq & 1) << 3);
            ldsm_x4t(smem_u32(&sPh[rowc * 136 + colm]), ah[mt]);
            ldsm_x4t(smem_u32(&sPl[rowc * 136 + colm]), al[mt]);
        }
#pragma unroll
        for (int j = 0; j < 4; j++) {
            int rowc = c0 + ((bq & 1) << 3) + br;
            int coln = (nw << 6) + (j << 4) + ((bq >> 1) << 3);
            uint32_t bh[4], bl[4];
            ldsm_x4t(smem_u32(&sTh[rowc * 136 + coln]), bh);
            ldsm_x4t(smem_u32(&sTl[rowc * 136 + coln]), bl);
#pragma unroll
            for (int mt = 0; mt < 2; mt++) {
                mma_bf16(acc[mt][j * 2], ah[mt], bh[0], bh[1]);
                mma_bf16(acc[mt][j * 2 + 1], ah[mt], bh[2], bh[3]);
                mma_bf16(acc[mt][j * 2], al[mt], bh[0], bh[1]);
                mma_bf16(acc[mt][j * 2 + 1], al[mt], bh[2], bh[3]);
                mma_bf16(acc[mt][j * 2], ah[mt], bl[0], bl[1]);
                mma_bf16(acc[mt][j * 2 + 1], ah[mt], bl[2], bl[3]);
            }
        }
    }

    __syncthreads();
    __nv_bfloat16* sEH = (__nv_bfloat16*)sm3;
    __nv_bfloat16* sEL = (__nv_bfloat16*)(sm3 + 34816);
#pragma unroll
    for (int mt = 0; mt < 2; mt++) {
        int krow = (kw << 5) + (mt << 4) + (lane >> 2);
        float sA = 0.f, sB = 0.f;
#pragma unroll
        for (int j = 0; j < 8; j++) {
            int nc = (nw << 6) + (j << 3) + ((lane & 3) << 1);
            float ex = __expf(acc[mt][j].x), ey = __expf(acc[mt][j].y);
            float ez = __expf(acc[mt][j].z), ew = __expf(acc[mt][j].w);
            sA += ex + ey; sB += ez + ew;
            uint32_t h0, l0, h1, l1;
            split2(ex, ey, h0, l0);
            split2(ez, ew, h1, l1);
            *(uint32_t*)&sEH[krow * 136 + nc] = h0;
            *(uint32_t*)&sEL[krow * 136 + nc] = l0;
            *(uint32_t*)&sEH[(krow + 8) * 136 + nc] = h1;
            *(uint32_t*)&sEL[(krow + 8) * 136 + nc] = l1;
        }
        sA += __shfl_xor_sync(0xffffffffu, sA, 1);
        sA += __shfl_xor_sync(0xffffffffu, sA, 2);
        sB += __shfl_xor_sync(0xffffffffu, sB, 1);
        sB += __shfl_xor_sync(0xffffffffu, sB, 2);
        if ((lane & 3) == 0) {
            atomicAdd(&g_Z[b * Nn + k0 + krow], sA);
            atomicAdd(&g_Z[b * Nn + k0 + krow + 8], sB);
        }
    }
    __syncthreads();
#pragma unroll
    for (int i = 0; i < 8; i++) {
        int lin = t + (i << 8);
        int r = lin >> 4, q = lin & 15;
        size_t off = ((size_t)(b * Nn + k0 + r)) * Nn + n0 + (q << 3);
        *(uint4*)&g_EH[off] = *(uint4*)&sEH[r * 136 + (q << 3)];
        *(uint4*)&g_EL[off] = *(uint4*)&sEL[r * 136 + (q << 3)];
    }
}

// ---------------- K5: gz = (wmask@gm)/Z via mma.sync, bf16 hi/lo out --------
__global__ __launch_bounds__(256, 2) void k5_gmz_mma(void) {
    extern __shared__ __align__(16) char sm5[];
    __nv_bfloat16* sGh = (__nv_bfloat16*)sm5;
    __nv_bfloat16* sGl = (__nv_bfloat16*)(sm5 + 17408);
    __nv_bfloat16* sWh = (__nv_bfloat16*)(sm5 + 34816);
    __nv_bfloat16* sWl = (__nv_bfloat16*)(sm5 + 44032);
    float* szm = (float*)(sm5 + 53248);
    int b = blockIdx.x, m0 = blockIdx.y << 7;
    int t = threadIdx.x, w = t >> 5, lane = t & 31;
    int ogrp = w & 3, mgrp = w >> 2;

    const float* gm = g_gm + (size_t)(b << 6) * Nn;
#pragma unroll
    for (int i = 0; i < 8; i++) {
        int lin = t + (i << 8);
        int r = lin >> 5, q = lin & 31;
        float4 v = *(const float4*)&gm[(size_t)r * Nn + m0 + (q << 2)];
        uint2 hi, lo;
        split4(v, hi, lo);
        *(uint2*)&sGh[r * 136 + (q << 2)] = hi;
        *(uint2*)&sGl[r * 136 + (q << 2)] = lo;
    }
#pragma unroll
    for (int i = 0; i < 2; i++) {
        int lin = t + (i << 8);
        int r = lin >> 3, q = lin & 7;
        *(uint4*)&sWh[r * 72 + (q << 3)] = *(const uint4*)&g_wmaskH[r * 64 + (q << 3)];
        *(uint4*)&sWl[r * 72 + (q << 3)] = *(const uint4*)&g_wmaskL[r * 64 + (q << 3)];
    }
    if (t < 128) szm[t] = 1.0f / g_Z[b * Nn + m0 + t];
    __syncthreads();

    int lr = lane & 15, lh = lane >> 4;
    int bq = lane >> 3, br = lane & 7;

    float4 acc[8] = {};
#pragma unroll
    for (int kk = 0; kk < 4; kk++) {
        uint32_t ah[4], al[4];
        ldsm_x4(smem_u32(&sWh[(ogrp * 16 + lr) * 72 + kk * 16 + lh * 8]), ah);
        ldsm_x4(smem_u32(&sWl[(ogrp * 16 + lr) * 72 + kk * 16 + lh * 8]), al);
#pragma unroll
        for (int j = 0; j < 4; j++) {
            int rowk = (kk << 4) + ((bq & 1) << 3) + br;
            int colm = (mgrp << 6) + (j << 4) + ((bq >> 1) << 3);
            uint32_t bh[4], bl[4];
            ldsm_x4t(smem_u32(&sGh[rowk * 136 + colm]), bh);
            mma_bf16(acc[j * 2], ah, bh[0], bh[1]);
            mma_bf16(acc[j * 2 + 1], ah, bh[2], bh[3]);
            mma_bf16(acc[j * 2], al, bh[0], bh[1]);
            mma_bf16(acc[j * 2 + 1], al, bh[2], bh[3]);
            ldsm_x4t(smem_u32(&sGl[rowk * 136 + colm]), bl);
            mma_bf16(acc[j * 2], ah, bl[0], bl[1]);
            mma_bf16(acc[j * 2 + 1], ah, bl[2], bl[3]);
        }
    }
    int o = (ogrp << 4) + (lane >> 2);
    size_t rowa = ((size_t)(b << 6) + o) * Nn + m0;
    size_t rowb2 = ((size_t)(b << 6) + o + 8) * Nn + m0;
#pragma unroll
    for (int f = 0; f < 8; f++) {
        int mm = (mgrp << 6) + ((f >> 1) << 4) + ((f & 1) << 3) + ((lane & 3) << 1);
        float i0 = szm[mm], i1 = szm[mm + 1];
        uint32_t h, l;
        split2(acc[f].x * i0, acc[f].y * i1, h, l);
        *(uint32_t*)&g_gzH[rowa + mm] = h;
        *(uint32_t*)&g_gzL[rowa + mm] = l;
        split2(acc[f].z * i0, acc[f].w * i1, h, l);
        *(uint32_t*)&g_gzH[rowb2 + mm] = h;
        *(uint32_t*)&g_gzL[rowb2 + mm] = l;
    }
}

// ---------------- K4: out = gz @ E + x (4 warps, 16o x 128n, cp.async) ------
__global__ __launch_bounds__(128, 2) void k4_out_mma(
    const float* __restrict__ x, float* __restrict__ out) {
    extern __shared__ __align__(16) char sm4[];
    uint32_t sb = smem_u32(sm4);
    int b = blockIdx.x, n0 = blockIdx.y << 7;
    int t = threadIdx.x, w = t >> 5, lane = t & 31;

    float4 acc[16] = {};
    int lr = lane & 15, lh = lane >> 4;
    int bq = lane >> 3, br = lane & 7;

    auto stage = [&](int mc, int buf) {
        uint32_t base = sb + buf * 53248u;
        uint32_t aH = base, aL = base + 9216u, bH = base + 18432u, bL = base + 35840u;
#pragma unroll
        for (int i = 0; i < 4; i++) {
            int lin = t + (i << 7);
            int r = lin >> 3, q = lin & 7;
            size_t gofs = ((size_t)(b << 6) + r) * Nn + mc + (q << 3);
            cpa16(aH + r * 144 + (q << 4), &g_gzH[gofs]);
            cpa16(aL + r * 144 + (q << 4), &g_gzL[gofs]);
        }
#pragma unroll
        for (int i = 0; i < 8; i++) {
            int lin = t + (i << 7);
            int r = lin >> 4, q = lin & 15;
            size_t off = ((size_t)(b * Nn) + mc + r) * Nn + n0 + (q << 3);
            cpa16(bH + r * 272 + (q << 4), &g_EH[off]);
            cpa16(bL + r * 272 + (q << 4), &g_EL[off]);
        }
        CPA_COMMIT();
    };

    stage(0, 0);
    for (int ci = 0; ci < 16; ci++) {
        int buf = ci & 1;
        if (ci + 1 < 16) { stage((ci + 1) << 6, buf ^ 1); CPA_WAIT(1); }
        else { CPA_WAIT(0); }
        __syncthreads();
        uint32_t base = sb + buf * 53248u;
        uint32_t aH = base, aL = base + 9216u, bH = base + 18432u, bL = base + 35840u;
#pragma unroll
        for (int kk = 0; kk < 4; kk++) {
            uint32_t ah[4], al[4];
            uint32_t arow = (w * 16 + lr) * 144 + kk * 32 + lh * 16;
            ldsm_x4(aH + arow, ah);
            ldsm_x4(aL + arow, al);
#pragma unroll
            for (int j = 0; j < 8; j++) {
                int rowm = (kk << 4) + ((bq & 1) << 3) + br;
                int coln = (j << 4) + ((bq >> 1) << 3);
                uint32_t boff = rowm * 272 + coln * 2;
                uint32_t bh[4], bl[4];
                ldsm_x4t(bH + boff, bh);
                mma_bf16(acc[j * 2], ah, bh[0], bh[1]);
                mma_bf16(acc[j * 2 + 1], ah, bh[2], bh[3]);
                mma_bf16(acc[j * 2], al, bh[0], bh[1]);
                mma_bf16(acc[j * 2 + 1], al, bh[2], bh[3]);
                ldsm_x4t(bL + boff, bl);
                mma_bf16(acc[j * 2], ah, bl[0], bl[1]);
                mma_bf16(acc[j * 2 + 1], ah, bl[2], bl[3]);
            }
        }
        __syncthreads();
    }
    int o = (w << 4) + (lane >> 2);
#pragma unroll
    for (int f = 0; f < 16; f++) {
        int n = n0 + ((f >> 1) << 4) + ((f & 1) << 3) + ((lane & 3) << 1);
        size_t off = ((size_t)(b << 6) + o) * Nn + n;
        float2 xv = *(const float2*)&x[off];
        *(float2*)&out[off] = make_float2(acc[f].x + xv.x, acc[f].y + xv.y);
        size_t off2 = off + (size_t)8 * Nn;
        float2 xv2 = *(const float2*)&x[off2];
        *(float2*)&out[off2] = make_float2(acc[f].z + xv2.x, acc[f].w + xv2.y);
    }
}

// ---------------- launch ----------------------------------------------------
extern "C" void kernel_launch(void* const* d_in, const int* in_sizes, int n_in,
                              void* d_out, int out_size) {
    const float* x      = (const float*)d_in[0];
    const float* wphi   = (const float*)d_in[1];
    const float* wtheta = (const float*)d_in[2];
    const float* wg     = (const float*)d_in[3];
    const float* wmask  = (const float*)d_in[4];
    const float* wmv    = (const float*)d_in[5];
    const float* wmk    = (const float*)d_in[6];
    float* out = (float*)d_out;

    cudaFuncSetAttribute(k1_mma, cudaFuncAttributeMaxDynamicSharedMemorySize, 90112);
    cudaFuncSetAttribute(k2_P_mma, cudaFuncAttributeMaxDynamicSharedMemorySize, 110592);
    cudaFuncSetAttribute(k3_att_mma, cudaFuncAttributeMaxDynamicSharedMemorySize, 69632);
    cudaFuncSetAttribute(k5_gmz_mma, cudaFuncAttributeMaxDynamicSharedMemorySize, 53760);
    cudaFuncSetAttribute(k4_out_mma, cudaFuncAttributeMaxDynamicSharedMemorySize, 106496);

    k0_all<<<1024, 256>>>(wmk, wmv, wg, wphi, wtheta, wmask);
    k1_mma<<<dim3(32, 8), 256, 90112>>>(x);
    k2_P_mma<<<dim3(32, 8), 128, 110592>>>();
    k3_att_mma<<<dim3(8, 8, 32), 256, 69632>>>();
    k5_gmz_mma<<<dim3(32, 8), 256, 53760>>>();
    k4_out_mma<<<dim3(32, 8), 128, 106496>>>(x, out);
}